// round 5
// baseline (speedup 1.0000x reference)
#include <cuda_runtime.h>
#include <cuda_bf16.h>

// out[i,j,:] = W[:,p] + W[:,66+t] + e*W[:,132] + W[:,133+s]
//
// Fused table (138 rows x 128 ch, channel-contiguous), as in R4:
//   T[r]     = W[:,r]  + W[:,131]     (r in 0..65)   covers (p, t=131)
//   T[66+dt] = W[:,32] + W[:,66+dt]   (dt in 0..65)  covers (p=32, t) [ri==rj]
//   T[132+k] = W[:,133+k] + (k<5 ? W[:,132] : 0)     entity-folded chain rows
// Hot loop: o = T[pt] + T[ch], where the dominant case (pt=65, ch=137) is
// served from registers with PREDICATED (inline-PTX) shared loads — zero
// smem wavefronts for ~66% of pairs, zero branches, stores stay in-order.

#define N_TBL_ROWS 138
#define CZ 128
#define NO_BINS 139
#define THREADS 256
#define ROWS_PER_CTA 2
#define E_DEFAULT 0x8941u   /* pt=65 | ch=137<<8 */

__device__ float g_tbl[N_TBL_ROWS * CZ];

__global__ void build_tbl_kernel(const float* __restrict__ W) {
    int idx = blockIdx.x * blockDim.x + threadIdx.x;
    if (idx >= N_TBL_ROWS * CZ) return;
    int row = idx >> 7;        // 0..137
    int c   = idx & (CZ - 1);  // 0..127
    const float* Wc = W + c * NO_BINS;
    float v;
    if (row < 66) {
        v = Wc[row] + Wc[131];
    } else if (row < 132) {
        v = Wc[32] + Wc[row];
    } else {
        int k = row - 132;
        v = Wc[133 + k];
        if (k < 5) v += Wc[132];
    }
    g_tbl[idx] = v;
}

__global__ __launch_bounds__(THREADS) void relpos_kernel(
    const int* __restrict__ asym,
    const int* __restrict__ res,
    const int* __restrict__ ent,
    const int* __restrict__ tok,
    const int* __restrict__ sym,
    float* __restrict__ out,
    int N)
{
    extern __shared__ float smem[];
    float*    s_tbl = smem;                                   // 138*128 floats
    unsigned* s_idx = (unsigned*)(smem + N_TBL_ROWS * CZ);    // ROWS_PER_CTA * N

    const int tid = threadIdx.x;
    const int i0  = blockIdx.x * ROWS_PER_CTA;

    // --- Prologue A: table -> SMEM (coalesced float4, conflict-free) ---
    {
        float4*       dst = (float4*)s_tbl;
        const float4* src = (const float4*)g_tbl;
        #pragma unroll
        for (int k = tid; k < (N_TBL_ROWS * CZ) / 4; k += THREADS) dst[k] = src[k];
    }

    // --- Prologue B: indices for both rows from ONE pass over j features ---
    const int ai0 = __ldg(asym + i0),     ai1 = __ldg(asym + i0 + 1);
    const int ri0 = __ldg(res  + i0),     ri1 = __ldg(res  + i0 + 1);
    const int ei0 = __ldg(ent  + i0),     ei1 = __ldg(ent  + i0 + 1);
    const int ti0 = __ldg(tok  + i0),     ti1 = __ldg(tok  + i0 + 1);
    const int si0 = __ldg(sym  + i0),     si1 = __ldg(sym  + i0 + 1);

    for (int j = tid; j < N; j += THREADS) {
        int aj = __ldg(asym + j);
        int rj = __ldg(res  + j);
        int ej = __ldg(ent  + j);
        int tj = __ldg(tok  + j);
        int sj = __ldg(sym  + j);

        {   // row i0
            bool sc = (ai0 == aj), sr = (ri0 == rj);
            int p  = min(max(ri0 - rj + 32, 0), 64);
            int dt = min(max(ti0 - tj + 32, 0), 64);
            int pt = sc ? (sr ? (66 + dt) : p) : 65;
            int ds = min(max(si0 - sj + 2, 0), 4);
            int ch = (ei0 == ej) ? (132 + ds) : 137;
            s_idx[j] = (unsigned)pt | ((unsigned)ch << 8);
        }
        {   // row i0+1
            bool sc = (ai1 == aj), sr = (ri1 == rj);
            int p  = min(max(ri1 - rj + 32, 0), 64);
            int dt = min(max(ti1 - tj + 32, 0), 64);
            int pt = sc ? (sr ? (66 + dt) : p) : 65;
            int ds = min(max(si1 - sj + 2, 0), 4);
            int ch = (ei1 == ej) ? (132 + ds) : 137;
            s_idx[N + j] = (unsigned)pt | ((unsigned)ch << 8);
        }
    }
    __syncthreads();

    // --- Hot phase ---
    const int warp = tid >> 5;
    const int lane = tid & 31;
    const float4* tbl4 = (const float4*)s_tbl;

    // u32 shared address of this lane's slice of table row 0
    unsigned tbl_base = (unsigned)__cvta_generic_to_shared(s_tbl) + (lane << 4);

    // default vector: T[65] + T[137], same add order as general path
    float4 a65  = tbl4[65  * 32 + lane];
    float4 c137 = tbl4[137 * 32 + lane];
    float4 dflt;
    dflt.x = a65.x + c137.x;
    dflt.y = a65.y + c137.y;
    dflt.z = a65.z + c137.z;
    dflt.w = a65.w + c137.w;

    // live-across-iterations operand registers for the predicated loads
    float ax = 0.f, ay = 0.f, az = 0.f, aw = 0.f;
    float cx = 0.f, cy = 0.f, cz = 0.f, cw = 0.f;

    for (int r = 0; r < ROWS_PER_CTA; r++) {
        const unsigned* idxp = s_idx + r * N;
        float* orow = out + (size_t)(i0 + r) * N * CZ + lane * 4;

        #pragma unroll 4
        for (int j = warp; j < N; j += (THREADS / 32)) {
            unsigned e = idxp[j];                 // LDS broadcast (warp-uniform)
            unsigned gen = (e != E_DEFAULT);      // warp-uniform 0/1
            unsigned pt = e & 0xFFu;
            unsigned ch = e >> 8;
            unsigned addrA = tbl_base + (pt << 9);   // row stride = 128 floats = 512 B
            unsigned addrC = tbl_base + (ch << 9);

            // Predicated v4 shared loads: when gen==0 (default pair), these
            // consume ZERO smem wavefronts and leave ax..cw untouched.
            asm("{\n\t"
                ".reg .pred p;\n\t"
                "setp.ne.u32 p, %8, 0;\n\t"
                "@p ld.shared.v4.f32 {%0,%1,%2,%3}, [%9];\n\t"
                "@p ld.shared.v4.f32 {%4,%5,%6,%7}, [%10];\n\t"
                "}"
                : "+f"(ax), "+f"(ay), "+f"(az), "+f"(aw),
                  "+f"(cx), "+f"(cy), "+f"(cz), "+f"(cw)
                : "r"(gen), "r"(addrA), "r"(addrC));

            float4 o;   // FSEL blend — no branches, stale a/c harmless when default
            o.x = gen ? (ax + cx) : dflt.x;
            o.y = gen ? (ay + cy) : dflt.y;
            o.z = gen ? (az + cz) : dflt.z;
            o.w = gen ? (aw + cw) : dflt.w;

            __stcs((float4*)(orow + (size_t)j * CZ), o);
        }
    }
}

extern "C" void kernel_launch(void* const* d_in, const int* in_sizes, int n_in,
                              void* d_out, int out_size) {
    const int*   asym = (const int*)d_in[0];
    const int*   res  = (const int*)d_in[1];
    const int*   ent  = (const int*)d_in[2];
    const int*   tok  = (const int*)d_in[3];
    const int*   sym  = (const int*)d_in[4];
    const float* W    = (const float*)d_in[5];
    float*       out  = (float*)d_out;

    const int N = in_sizes[0];  // 1024

    build_tbl_kernel<<<(N_TBL_ROWS * CZ + 255) / 256, 256>>>(W);

    const int smem_bytes = N_TBL_ROWS * CZ * (int)sizeof(float)
                         + ROWS_PER_CTA * N * (int)sizeof(unsigned);
    cudaFuncSetAttribute(relpos_kernel, cudaFuncAttributeMaxDynamicSharedMemorySize, smem_bytes);
    relpos_kernel<<<N / ROWS_PER_CTA, THREADS, smem_bytes>>>(asym, res, ent, tok, sym, out, N);
}

// round 7
// speedup vs baseline: 1.3920x; 1.3920x over previous
#include <cuda_runtime.h>
#include <cuda_bf16.h>

// out[i,j,:] = W[:,p] + W[:,66+t] + e*W[:,132] + W[:,133+s]
//
// Fused table (138 rows x 128 ch, channel-contiguous), as in R4:
//   T[r]     = W[:,r]  + W[:,131]     (r in 0..65)   covers (p, t=131)
//   T[66+dt] = W[:,32] + W[:,66+dt]   (dt in 0..65)  covers (p=32, t) [ri==rj]
//   T[132+k] = W[:,133+k] + (k<5 ? W[:,132] : 0)     entity-folded chain rows
//
// R6: table stays in GLOBAL memory, read via __ldg -> L1D-resident (70KB fits
// in 228KB L1, persists across CTAs within the launch). SMEM holds only the
// 4KB per-row index array -> 8 CTAs/SM instead of ~3 -> 3x store MLP.
// Hot loop identical in shape to R4: branch-free, in-order, 2 loads + 1 store.

#define N_TBL_ROWS 138
#define CZ 128
#define NO_BINS 139
#define THREADS 256

__device__ float g_tbl[N_TBL_ROWS * CZ];

__global__ void build_tbl_kernel(const float* __restrict__ W) {
    int idx = blockIdx.x * blockDim.x + threadIdx.x;
    if (idx >= N_TBL_ROWS * CZ) return;
    int row = idx >> 7;        // 0..137
    int c   = idx & (CZ - 1);  // 0..127
    const float* Wc = W + c * NO_BINS;
    float v;
    if (row < 66) {
        v = Wc[row] + Wc[131];            // (p, t=131) fused
    } else if (row < 132) {
        v = Wc[32] + Wc[row];             // (p=32, t) fused (ri==rj case)
    } else {
        int k = row - 132;                // 0..5
        v = Wc[133 + k];
        if (k < 5) v += Wc[132];          // entity flag folded in
    }
    g_tbl[idx] = v;
}

__global__ __launch_bounds__(THREADS) void relpos_kernel(
    const int* __restrict__ asym,
    const int* __restrict__ res,
    const int* __restrict__ ent,
    const int* __restrict__ tok,
    const int* __restrict__ sym,
    float* __restrict__ out,
    int N)
{
    __shared__ unsigned s_idx[1024];     // per-j packed (pt, ch)

    const int tid = threadIdx.x;
    const int i   = blockIdx.x;

    // --- Prologue: per-j fused indices for this row i ---
    const int ai = __ldg(asym + i);
    const int ri = __ldg(res  + i);
    const int ei = __ldg(ent  + i);
    const int ti = __ldg(tok  + i);
    const int si = __ldg(sym  + i);

    for (int j = tid; j < N; j += THREADS) {
        int aj = __ldg(asym + j);
        int rj = __ldg(res  + j);
        int ej = __ldg(ent  + j);
        int tj = __ldg(tok  + j);
        int sj = __ldg(sym  + j);

        bool sc = (ai == aj);
        bool sr = (ri == rj);

        int p  = min(max(ri - rj + 32, 0), 64);   // 0..64
        int dt = min(max(ti - tj + 32, 0), 64);   // 0..64
        int pt = sc ? (sr ? (66 + dt) : p) : 65;

        int ds = min(max(si - sj + 2, 0), 4);
        int ch = (ei == ej) ? (132 + ds) : 137;

        s_idx[j] = (unsigned)pt | ((unsigned)ch << 8);
    }
    __syncthreads();

    // --- Hot loop: warp-per-pair, in-order, branch-free ---
    // 2 x LDG.128 (L1-resident table) + 1 x STG.128 per pair.
    const int warp = tid >> 5;
    const int lane = tid & 31;
    const float4* tbl4 = (const float4*)g_tbl;   // row stride = 32 float4
    float* orow = out + (size_t)i * N * CZ + lane * 4;

    #pragma unroll 4
    for (int j = warp; j < N; j += (THREADS / 32)) {
        unsigned pk = s_idx[j];
        int pt = pk & 0xFFu;
        int ch = pk >> 8;

        float4 a = __ldg(tbl4 + pt * 32 + lane);
        float4 c = __ldg(tbl4 + ch * 32 + lane);

        float4 o;
        o.x = a.x + c.x;
        o.y = a.y + c.y;
        o.z = a.z + c.z;
        o.w = a.w + c.w;

        __stcs((float4*)(orow + (size_t)j * CZ), o);
    }
}

extern "C" void kernel_launch(void* const* d_in, const int* in_sizes, int n_in,
                              void* d_out, int out_size) {
    const int*   asym = (const int*)d_in[0];
    const int*   res  = (const int*)d_in[1];
    const int*   ent  = (const int*)d_in[2];
    const int*   tok  = (const int*)d_in[3];
    const int*   sym  = (const int*)d_in[4];
    const float* W    = (const float*)d_in[5];
    float*       out  = (float*)d_out;

    const int N = in_sizes[0];  // 1024

    build_tbl_kernel<<<(N_TBL_ROWS * CZ + 255) / 256, 256>>>(W);
    relpos_kernel<<<N, THREADS>>>(asym, res, ent, tok, sym, out, N);
}

// round 8
// speedup vs baseline: 1.5163x; 1.0893x over previous
#include <cuda_runtime.h>
#include <cuda_bf16.h>

// out[i,j,:] = W[:,p] + W[:,66+t] + e*W[:,132] + W[:,133+s]
//
// Fused table (138 rows x 128 ch, channel-contiguous), as in R4:
//   T[r]     = W[:,r]  + W[:,131]     (r in 0..65)   covers (p, t=131)
//   T[66+dt] = W[:,32] + W[:,66+dt]   (dt in 0..65)  covers (p=32, t) [ri==rj]
//   T[132+k] = W[:,133+k] + (k<5 ? W[:,132] : 0)     entity-folded chain rows
// Hot loop: o = T[pt] + T[ch] -> 2 LDS.128 + 1 STG.128, branch-free, in-order.
//
// R7 = R4 with THREADS 256 -> 512: same SMEM/CTA (74.6KB), still 3 CTAs/SM,
// but 48 warps/SM instead of 24 -> 2x store MLP. Hot loop untouched.

#define N_TBL_ROWS 138
#define CZ 128
#define NO_BINS 139
#define THREADS 512
#define NWARPS (THREADS / 32)

__device__ float g_tbl[N_TBL_ROWS * CZ];

__global__ void build_tbl_kernel(const float* __restrict__ W) {
    int idx = blockIdx.x * blockDim.x + threadIdx.x;
    if (idx >= N_TBL_ROWS * CZ) return;
    int row = idx >> 7;        // 0..137
    int c   = idx & (CZ - 1);  // 0..127
    const float* Wc = W + c * NO_BINS;
    float v;
    if (row < 66) {
        v = Wc[row] + Wc[131];            // (p, t=131) fused
    } else if (row < 132) {
        v = Wc[32] + Wc[row];             // (p=32, t) fused (ri==rj case)
    } else {
        int k = row - 132;                // 0..5
        v = Wc[133 + k];
        if (k < 5) v += Wc[132];          // entity flag folded in
    }
    g_tbl[idx] = v;
}

__global__ __launch_bounds__(THREADS, 3) void relpos_kernel(
    const int* __restrict__ asym,
    const int* __restrict__ res,
    const int* __restrict__ ent,
    const int* __restrict__ tok,
    const int* __restrict__ sym,
    float* __restrict__ out,
    int N)
{
    extern __shared__ float smem[];
    float*    s_tbl = smem;                                   // 138*128 floats
    unsigned* s_idx = (unsigned*)(smem + N_TBL_ROWS * CZ);    // N packed indices

    const int tid = threadIdx.x;
    const int i   = blockIdx.x;

    // --- Prologue A: table -> SMEM (coalesced float4, conflict-free) ---
    {
        float4*       dst = (float4*)s_tbl;
        const float4* src = (const float4*)g_tbl;
        #pragma unroll
        for (int k = tid; k < (N_TBL_ROWS * CZ) / 4; k += THREADS) dst[k] = src[k];
    }

    // --- Prologue B: per-j fused indices (pt, ch) packed into one u32 ---
    const int ai = __ldg(asym + i);
    const int ri = __ldg(res  + i);
    const int ei = __ldg(ent  + i);
    const int ti = __ldg(tok  + i);
    const int si = __ldg(sym  + i);

    for (int j = tid; j < N; j += THREADS) {
        int aj = __ldg(asym + j);
        int rj = __ldg(res  + j);
        int ej = __ldg(ent  + j);
        int tj = __ldg(tok  + j);
        int sj = __ldg(sym  + j);

        bool sc = (ai == aj);
        bool sr = (ri == rj);

        int p  = min(max(ri - rj + 32, 0), 64);   // 0..64
        int dt = min(max(ti - tj + 32, 0), 64);   // 0..64
        int pt = sc ? (sr ? (66 + dt) : p) : 65;

        int ds = min(max(si - sj + 2, 0), 4);
        int ch = (ei == ej) ? (132 + ds) : 137;

        s_idx[j] = (unsigned)pt | ((unsigned)ch << 8);
    }
    __syncthreads();

    // --- Hot loop: warp-per-pair, in-order, branch-free: 2 LDS.128 + STG.128 ---
    const int warp = tid >> 5;
    const int lane = tid & 31;
    const float4* tbl4 = (const float4*)s_tbl;
    float* orow = out + (size_t)i * N * CZ + lane * 4;

    #pragma unroll 4
    for (int j = warp; j < N; j += NWARPS) {
        unsigned pk = s_idx[j];
        int pt = pk & 0xFFu;
        int ch = pk >> 8;

        float4 a = tbl4[pt * 32 + lane];
        float4 c = tbl4[ch * 32 + lane];

        float4 o;
        o.x = a.x + c.x;
        o.y = a.y + c.y;
        o.z = a.z + c.z;
        o.w = a.w + c.w;

        __stcs((float4*)(orow + (size_t)j * CZ), o);
    }
}

extern "C" void kernel_launch(void* const* d_in, const int* in_sizes, int n_in,
                              void* d_out, int out_size) {
    const int*   asym = (const int*)d_in[0];
    const int*   res  = (const int*)d_in[1];
    const int*   ent  = (const int*)d_in[2];
    const int*   tok  = (const int*)d_in[3];
    const int*   sym  = (const int*)d_in[4];
    const float* W    = (const float*)d_in[5];
    float*       out  = (float*)d_out;

    const int N = in_sizes[0];  // 1024

    build_tbl_kernel<<<(N_TBL_ROWS * CZ + 255) / 256, 256>>>(W);

    const int smem_bytes = N_TBL_ROWS * CZ * (int)sizeof(float) + N * (int)sizeof(unsigned);
    cudaFuncSetAttribute(relpos_kernel, cudaFuncAttributeMaxDynamicSharedMemorySize, smem_bytes);
    relpos_kernel<<<N, THREADS, smem_bytes>>>(asym, res, ent, tok, sym, out, N);
}